// round 3
// baseline (speedup 1.0000x reference)
#include <cuda_runtime.h>
#include <cstdint>
#include <math_constants.h>

#define NN   1024     // N (square)
#define BB   128      // batch
#define SPLITK 8
#define KS   (NN / SPLITK)   // 128 k per block
#define BK   32              // k chunk in smem
#define NCH  (KS / BK)       // 4 chunks
#define BM   64              // b tile per block
#define BN   64              // j tile per block
#define XS_STRIDE 68         // conflict-free padded stride

// encoded-max accumulator: [BB][NN] = 0.5 MB
__device__ unsigned int g_enc[BB * NN];

#define ENC_NEG_INF 0x007FFFFFu   // enc(-inf)

__device__ __forceinline__ unsigned int enc_f32(float f) {
    unsigned int u = __float_as_uint(f);
    return (u & 0x80000000u) ? ~u : (u | 0x80000000u);
}
__device__ __forceinline__ float dec_f32(unsigned int e) {
    return __uint_as_float((e & 0x80000000u) ? (e ^ 0x80000000u) : ~e);
}

__device__ __forceinline__ void cp_async16(uint32_t dst_smem, const void* src) {
    asm volatile("cp.async.cg.shared.global [%0], [%1], 16;\n"
                 :: "r"(dst_smem), "l"(src));
}
__device__ __forceinline__ void cp_commit() {
    asm volatile("cp.async.commit_group;\n" ::: "memory");
}
__device__ __forceinline__ void cp_wait0() {
    asm volatile("cp.async.wait_group 0;\n" ::: "memory");
}

__global__ void __launch_bounds__(256, 4)
tropical_init()
{
    const int i = (blockIdx.x * 256 + threadIdx.x) << 2;
    uint4 v = make_uint4(ENC_NEG_INF, ENC_NEG_INF, ENC_NEG_INF, ENC_NEG_INF);
    *reinterpret_cast<uint4*>(&g_enc[i]) = v;
}

__global__ void __launch_bounds__(256, 2)
tropical_main(const float* __restrict__ x,
              const float* __restrict__ w)
{
    __shared__ float xs[2][BK][XS_STRIDE];  // x transposed: [k][b]
    __shared__ float ws[2][BK][BN];         // w natural:    [k][j]

    const int tid = threadIdx.x;
    const int tx  = tid & 15;        // j quad (0..15)
    const int ty  = tid >> 4;        // b quad (0..15)
    const int j0  = blockIdx.x * BN;
    const int b0  = blockIdx.y * BM;
    const int k0  = blockIdx.z * KS;

    // x load mapping: 2 float4 per thread per chunk
    const int lb  = tid >> 3;              // 0..31 then +32
    const int lf4 = (tid & 7) << 2;        // 0..28 step 4
    // w load mapping: 2 cp.async per thread per chunk
    const int wk  = tid >> 4;              // 0..15 then +16
    const int wj  = (tid & 15) << 2;       // 0..60

    float acc[4][4];
    #pragma unroll
    for (int r = 0; r < 4; r++)
        #pragma unroll
        for (int c = 0; c < 4; c++)
            acc[r][c] = -CUDART_INF_F;

    // ---- prologue: chunk 0 into buffer 0 ----
    {
        #pragma unroll
        for (int h = 0; h < 2; h++) {
            const int bb = lb + 32 * h;
            float4 xr = *reinterpret_cast<const float4*>(&x[(b0 + bb) * NN + k0 + lf4]);
            xs[0][lf4 + 0][bb] = xr.x;
            xs[0][lf4 + 1][bb] = xr.y;
            xs[0][lf4 + 2][bb] = xr.z;
            xs[0][lf4 + 3][bb] = xr.w;
            uint32_t d = (uint32_t)__cvta_generic_to_shared(&ws[0][wk + 16 * h][wj]);
            cp_async16(d, &w[(k0 + wk + 16 * h) * NN + j0 + wj]);
        }
        cp_commit();
        cp_wait0();
        __syncthreads();
    }

    int buf = 0;
    #pragma unroll 1
    for (int c = 0; c < NCH; c++) {
        float4 xn0, xn1;
        const bool more = (c + 1 < NCH);
        if (more) {
            const int kb = k0 + (c + 1) * BK;
            xn0 = *reinterpret_cast<const float4*>(&x[(b0 + lb) * NN + kb + lf4]);
            xn1 = *reinterpret_cast<const float4*>(&x[(b0 + lb + 32) * NN + kb + lf4]);
            #pragma unroll
            for (int h = 0; h < 2; h++) {
                uint32_t d = (uint32_t)__cvta_generic_to_shared(&ws[buf ^ 1][wk + 16 * h][wj]);
                cp_async16(d, &w[(kb + wk + 16 * h) * NN + j0 + wj]);
            }
            cp_commit();
        }

        #pragma unroll 16
        for (int k = 0; k < BK; k++) {
            float4 xv = *reinterpret_cast<const float4*>(&xs[buf][k][ty << 2]);
            float4 wv = *reinterpret_cast<const float4*>(&ws[buf][k][tx << 2]);
            float xr4[4] = {xv.x, xv.y, xv.z, xv.w};
            float wc4[4] = {wv.x, wv.y, wv.z, wv.w};
            #pragma unroll
            for (int r = 0; r < 4; r++)
                #pragma unroll
                for (int cc = 0; cc < 4; cc++)
                    acc[r][cc] = fmaxf(acc[r][cc], xr4[r] - wc4[cc]);
        }

        if (more) {
            xs[buf ^ 1][lf4 + 0][lb] = xn0.x;
            xs[buf ^ 1][lf4 + 1][lb] = xn0.y;
            xs[buf ^ 1][lf4 + 2][lb] = xn0.z;
            xs[buf ^ 1][lf4 + 3][lb] = xn0.w;
            xs[buf ^ 1][lf4 + 0][lb + 32] = xn1.x;
            xs[buf ^ 1][lf4 + 1][lb + 32] = xn1.y;
            xs[buf ^ 1][lf4 + 2][lb + 32] = xn1.z;
            xs[buf ^ 1][lf4 + 3][lb + 32] = xn1.w;
            cp_wait0();
        }
        __syncthreads();
        buf ^= 1;
    }

    // ---- atomic-max epilogue (encoded uint, no return needed) ----
    #pragma unroll
    for (int r = 0; r < 4; r++) {
        unsigned int* row = &g_enc[(b0 + (ty << 2) + r) * NN + j0 + (tx << 2)];
        #pragma unroll
        for (int cc = 0; cc < 4; cc++)
            atomicMax(&row[cc], enc_f32(acc[r][cc]));
    }
}

__global__ void __launch_bounds__(256, 4)
tropical_decode(const float* __restrict__ bias,
                float* __restrict__ out)
{
    const int i = (blockIdx.x * 256 + threadIdx.x) << 2;
    uint4 e = *reinterpret_cast<const uint4*>(&g_enc[i]);
    const int j = i & (NN - 1);
    float4 bv = *reinterpret_cast<const float4*>(&bias[j]);
    float4 o;
    o.x = dec_f32(e.x) + bv.x;
    o.y = dec_f32(e.y) + bv.y;
    o.z = dec_f32(e.z) + bv.z;
    o.w = dec_f32(e.w) + bv.w;
    *reinterpret_cast<float4*>(&out[i]) = o;
}

extern "C" void kernel_launch(void* const* d_in, const int* in_sizes, int n_in,
                              void* d_out, int out_size) {
    const float* x    = (const float*)d_in[0];   // [128, 1024]
    const float* wgt  = (const float*)d_in[1];   // [1024, 1024]
    const float* bias = (const float*)d_in[2];   // [1024]
    float* out = (float*)d_out;                  // [128, 1024]

    const int total = BB * NN;                   // 131072

    tropical_init<<<total / 4 / 256, 256>>>();

    dim3 grid(NN / BN, BB / BM, SPLITK);         // (16, 2, 8) = 256 blocks
    tropical_main<<<grid, 256>>>(x, wgt);

    tropical_decode<<<total / 4 / 256, 256>>>(bias, out);
}